// round 1
// baseline (speedup 1.0000x reference)
#include <cuda_runtime.h>
#include <cstdint>

// Problem dims
constexpr int Lt = 128;          // timesteps
constexpr int Bt = 128;          // batch
constexpr int Af = 512;          // action features
constexpr int If = 512;          // input features
constexpr int Hd = 1024;         // hidden
constexpr int Gd = 4 * Hd;       // 4096 gate rows
constexpr int Kx = If + Af;      // 1024 (concat K)

// Scratch (static device allocations are allowed)
__device__ float g_gatesx[(size_t)Lt * Bt * Gd];   // 256 MB: precomputed x-side gates
__device__ float g_hbuf[2][Bt * Hd];               // double-buffered h broadcast
__device__ unsigned g_bar_count;
__device__ unsigned g_bar_gen;

__device__ __forceinline__ uint32_t f2tf(float x) {
    uint32_t u;
    asm volatile("cvt.rna.tf32.f32 %0, %1;" : "=r"(u) : "f"(x));
    return u;
}
__device__ __forceinline__ float f2tf_f(float x) { return __uint_as_float(f2tf(x)); }

__device__ __forceinline__ void mma8(float* c,
                                     uint32_t a0, uint32_t a1, uint32_t a2, uint32_t a3,
                                     uint32_t b0, uint32_t b1) {
    asm volatile(
        "mma.sync.aligned.m16n8k8.row.col.f32.tf32.tf32.f32 "
        "{%0,%1,%2,%3},{%4,%5,%6,%7},{%8,%9},{%0,%1,%2,%3};"
        : "+f"(c[0]), "+f"(c[1]), "+f"(c[2]), "+f"(c[3])
        : "r"(a0), "r"(a1), "r"(a2), "r"(a3), "r"(b0), "r"(b1));
}

__device__ __forceinline__ float sigm(float x) { return 1.0f / (1.0f + expf(-x)); }

// ============================================================================
// Phase 1: gates_x[m, g] = sum_k X[m,k] * W_ih[g,k]   (m = l*B + b)
// X[m, k<512] = input_feature[b, k]; X[m, k>=512] = action_features[m, k-512]
// tf32 mma tiled GEMM: BM=128, BN=128, BK=16, 256 threads
// ============================================================================
constexpr int BM = 128, BN = 128, BK = 16;

__global__ void __launch_bounds__(256, 1) gemm_x_kernel(
    const float* __restrict__ act, const float* __restrict__ inp,
    const float* __restrict__ Wih)
{
    // Reset grid barrier for phase 2 (phase 1 always completes first: same stream)
    if (blockIdx.x == 0 && blockIdx.y == 0 && threadIdx.x == 0) {
        g_bar_count = 0;
        g_bar_gen = 0;
    }

    __shared__ float As[BM][BK + 4];
    __shared__ float Bs[BN][BK + 4];

    const int tid  = threadIdx.x;
    const int lane = tid & 31;
    const int warp = tid >> 5;
    const int wm = warp & 3;       // 4 M-warps x 32 rows
    const int wn = warp >> 2;      // 2 N-warps x 64 cols
    const int bm = blockIdx.y * BM;
    const int bn = blockIdx.x * BN;

    float acc[2][8][4];
    #pragma unroll
    for (int i = 0; i < 2; i++)
        #pragma unroll
        for (int j = 0; j < 8; j++)
            #pragma unroll
            for (int k = 0; k < 4; k++) acc[i][j][k] = 0.0f;

    const int ldrow = tid >> 1;          // 0..127
    const int ldk   = (tid & 1) * 8;     // 0 or 8
    const int am = bm + ldrow;           // global m row for A load
    const int ab = am & (Bt - 1);        // batch index (BM==Bt so ab==ldrow)
    const int bnrow = bn + ldrow;        // global gate row for B load

    for (int kb = 0; kb < Kx; kb += BK) {
        // --- load A tile (with concat + tf32 round) ---
        const float* asrc = (kb < If)
            ? (inp + (size_t)ab * If + kb + ldk)
            : (act + (size_t)am * Af + (kb - If) + ldk);
        float4 va0 = *(const float4*)asrc;
        float4 va1 = *(const float4*)(asrc + 4);
        {
            float* d = &As[ldrow][ldk];
            d[0] = f2tf_f(va0.x); d[1] = f2tf_f(va0.y); d[2] = f2tf_f(va0.z); d[3] = f2tf_f(va0.w);
            d[4] = f2tf_f(va1.x); d[5] = f2tf_f(va1.y); d[6] = f2tf_f(va1.z); d[7] = f2tf_f(va1.w);
        }
        // --- load B tile (W_ih rows) ---
        const float* bsrc = Wih + (size_t)bnrow * Kx + kb + ldk;
        float4 vb0 = *(const float4*)bsrc;
        float4 vb1 = *(const float4*)(bsrc + 4);
        {
            float* d = &Bs[ldrow][ldk];
            d[0] = f2tf_f(vb0.x); d[1] = f2tf_f(vb0.y); d[2] = f2tf_f(vb0.z); d[3] = f2tf_f(vb0.w);
            d[4] = f2tf_f(vb1.x); d[5] = f2tf_f(vb1.y); d[6] = f2tf_f(vb1.z); d[7] = f2tf_f(vb1.w);
        }
        __syncthreads();

        #pragma unroll
        for (int ks = 0; ks < BK; ks += 8) {
            uint32_t a[2][4];
            #pragma unroll
            for (int tm = 0; tm < 2; tm++) {
                int r  = wm * 32 + tm * 16 + (lane >> 2);
                int kk = ks + (lane & 3);
                a[tm][0] = __float_as_uint(As[r][kk]);
                a[tm][1] = __float_as_uint(As[r + 8][kk]);
                a[tm][2] = __float_as_uint(As[r][kk + 4]);
                a[tm][3] = __float_as_uint(As[r + 8][kk + 4]);
            }
            #pragma unroll
            for (int tn = 0; tn < 8; tn++) {
                int cc = wn * 64 + tn * 8 + (lane >> 2);
                int kk = ks + (lane & 3);
                uint32_t b0 = __float_as_uint(Bs[cc][kk]);
                uint32_t b1 = __float_as_uint(Bs[cc][kk + 4]);
                mma8(acc[0][tn], a[0][0], a[0][1], a[0][2], a[0][3], b0, b1);
                mma8(acc[1][tn], a[1][0], a[1][1], a[1][2], a[1][3], b0, b1);
            }
        }
        __syncthreads();
    }

    // epilogue: raw gate projections (biases added in phase 2)
    #pragma unroll
    for (int tm = 0; tm < 2; tm++) {
        int r = bm + wm * 32 + tm * 16 + (lane >> 2);
        #pragma unroll
        for (int tn = 0; tn < 8; tn++) {
            int cc = bn + wn * 64 + tn * 8 + 2 * (lane & 3);
            *(float2*)&g_gatesx[(size_t)r * Gd + cc] =
                make_float2(acc[tm][tn][0], acc[tm][tn][1]);
            *(float2*)&g_gatesx[(size_t)(r + 8) * Gd + cc] =
                make_float2(acc[tm][tn][2], acc[tm][tn][3]);
        }
    }
}

// ============================================================================
// Phase 2: persistent LSTM recurrence. 128 CTAs x 256 threads, 1 CTA/SM.
// CTA j owns hidden units [8j, 8j+8): W_hh rows {u, H+u, 2H+u, 3H+u} in SMEM.
// Per step: gates_h = h @ Wslice^T (tf32 mma), cell update register-local,
// h broadcast via double-buffered global, one grid barrier per step.
// ============================================================================
constexpr int NTHR  = 256;
constexpr int WROWS = 32;
constexpr int WPAD  = Hd + 4;     // 1028 floats per W row (conflict-free frags)
constexpr int BK2   = 32;
constexpr int HTP   = BK2 + 4;    // 36
constexpr int SMEM2 = (WROWS * WPAD + Bt * HTP) * 4;   // 131584 + 18432 = 150016 B

__device__ __forceinline__ void gbar(unsigned target) {
    __syncthreads();
    if (threadIdx.x == 0) {
        __threadfence();
        unsigned old = atomicAdd(&g_bar_count, 1u);
        if ((old + 1u) % gridDim.x == 0u) {
            __threadfence();
            asm volatile("red.release.gpu.global.add.u32 [%0], %1;"
                         :: "l"(&g_bar_gen), "r"(1u) : "memory");
        } else {
            unsigned g;
            do {
                asm volatile("ld.acquire.gpu.global.u32 %0, [%1];"
                             : "=r"(g) : "l"(&g_bar_gen) : "memory");
            } while (g < target);
        }
        __threadfence();
    }
    __syncthreads();
}

__global__ void __launch_bounds__(NTHR, 1) lstm_seq_kernel(
    const float* __restrict__ h0, const float* __restrict__ c0in,
    const float* __restrict__ Whh, const float* __restrict__ bih,
    const float* __restrict__ bhh, float* __restrict__ out, int out_size)
{
    extern __shared__ float smemf[];
    float* Ws = smemf;                    // [32][WPAD] tf32-rounded W_hh slice
    float* Ht = smemf + WROWS * WPAD;     // [128][HTP] staged h chunk

    const int tid  = threadIdx.x;
    const int lane = tid & 31;
    const int warp = tid >> 5;
    const int cta  = blockIdx.x;
    const int ub   = cta * 8;                   // first hidden unit owned
    const int ul   = 2 * (lane & 3);            // local unit 0,2,4,6
    const int u0   = ub + ul;
    const int b0   = warp * 16 + (lane >> 2);   // batch row (c0/c1)

    // --- one-time: load W_hh slice, tf32-rounded.
    // local rows: [0..7]=i-gates, [8..15]=f, [16..23]=g, [24..31]=o (unit = row&7)
    for (int i = tid; i < WROWS * (Hd / 4); i += NTHR) {
        int lr = i >> 8;               // 0..31
        int c4 = (i & 255) * 4;
        int grow = (lr >> 3) * Hd + ub + (lr & 7);
        float4 v = *(const float4*)&Whh[(size_t)grow * Hd + c4];
        float* d = &Ws[lr * WPAD + c4];
        d[0] = f2tf_f(v.x); d[1] = f2tf_f(v.y); d[2] = f2tf_f(v.z); d[3] = f2tf_f(v.w);
    }

    // --- biases (b_ih + b_hh) for this thread's two units, all 4 gates
    float bias[4][2];
    #pragma unroll
    for (int q = 0; q < 4; q++) {
        bias[q][0] = bih[q * Hd + u0]     + bhh[q * Hd + u0];
        bias[q][1] = bih[q * Hd + u0 + 1] + bhh[q * Hd + u0 + 1];
    }

    // --- c state lives in registers for all 128 steps
    float creg[2][2];
    #pragma unroll
    for (int bs = 0; bs < 2; bs++) {
        int b = b0 + bs * 8;
        creg[bs][0] = c0in[(size_t)b * Hd + u0];
        creg[bs][1] = c0in[(size_t)b * Hd + u0 + 1];
    }

    // --- initial h broadcast (each CTA writes one batch row; tf32-rounded)
    for (int i = tid; i < Hd; i += NTHR)
        g_hbuf[0][cta * Hd + i] = f2tf_f(h0[cta * Hd + i]);
    gbar(1);

    const int ldrow = tid >> 1;
    const int ldk   = (tid & 1) * 16;

    for (int t = 0; t < Lt; t++) {
        const float* cur = g_hbuf[t & 1];
        float* nxt = g_hbuf[(t + 1) & 1];

        // prefetch this step's x-side gates (hidden behind the GEMM below)
        float2 gx[4][2];
        #pragma unroll
        for (int q = 0; q < 4; q++)
            #pragma unroll
            for (int bs = 0; bs < 2; bs++) {
                int b = b0 + bs * 8;
                gx[q][bs] = *(const float2*)
                    &g_gatesx[((size_t)t * Bt + b) * Gd + q * Hd + u0];
            }

        float acc[4][4];
        #pragma unroll
        for (int q = 0; q < 4; q++)
            #pragma unroll
            for (int k = 0; k < 4; k++) acc[q][k] = 0.0f;

        for (int kb = 0; kb < Hd; kb += BK2) {
            // stage h chunk [128][32] into SMEM
            const float4* s = (const float4*)&cur[ldrow * Hd + kb + ldk];
            float4 v0 = s[0], v1 = s[1], v2 = s[2], v3 = s[3];
            {
                float* d = &Ht[ldrow * HTP + ldk];
                d[0]=v0.x; d[1]=v0.y; d[2]=v0.z; d[3]=v0.w;
                d[4]=v1.x; d[5]=v1.y; d[6]=v1.z; d[7]=v1.w;
                d[8]=v2.x; d[9]=v2.y; d[10]=v2.z; d[11]=v2.w;
                d[12]=v3.x; d[13]=v3.y; d[14]=v3.z; d[15]=v3.w;
            }
            __syncthreads();
            #pragma unroll
            for (int ks = 0; ks < BK2; ks += 8) {
                int r  = warp * 16 + (lane >> 2);
                int kk = ks + (lane & 3);
                uint32_t a0 = __float_as_uint(Ht[r * HTP + kk]);
                uint32_t a1 = __float_as_uint(Ht[(r + 8) * HTP + kk]);
                uint32_t a2 = __float_as_uint(Ht[r * HTP + kk + 4]);
                uint32_t a3 = __float_as_uint(Ht[(r + 8) * HTP + kk + 4]);
                #pragma unroll
                for (int q = 0; q < 4; q++) {
                    int wr = q * 8 + (lane >> 2);
                    int wk = kb + ks + (lane & 3);
                    uint32_t bb0 = __float_as_uint(Ws[wr * WPAD + wk]);
                    uint32_t bb1 = __float_as_uint(Ws[wr * WPAD + wk + 4]);
                    mma8(acc[q], a0, a1, a2, a3, bb0, bb1);
                }
            }
            __syncthreads();
        }

        // cell update: all 4 gates of unit u sit in this thread (ci = bs*2+us)
        #pragma unroll
        for (int bs = 0; bs < 2; bs++) {
            int b = b0 + bs * 8;
            float hv[2], cv[2];
            #pragma unroll
            for (int us = 0; us < 2; us++) {
                int ci = bs * 2 + us;
                float gi = acc[0][ci] + (us ? gx[0][bs].y : gx[0][bs].x) + bias[0][us];
                float gf = acc[1][ci] + (us ? gx[1][bs].y : gx[1][bs].x) + bias[1][us];
                float gg = acc[2][ci] + (us ? gx[2][bs].y : gx[2][bs].x) + bias[2][us];
                float go = acc[3][ci] + (us ? gx[3][bs].y : gx[3][bs].x) + bias[3][us];
                float cn = sigm(gf) * creg[bs][us] + sigm(gi) * tanhf(gg);
                float hn = sigm(go) * tanhf(cn);
                creg[bs][us] = cn;
                hv[us] = hn;
                cv[us] = cn;
            }
            size_t ob = (size_t)t * Bt * Hd + (size_t)b * Hd + u0;
            *(float2*)&out[ob] = make_float2(hv[0], hv[1]);
            if (t + 1 < Lt) {
                *(float2*)&nxt[b * Hd + u0] = make_float2(f2tf_f(hv[0]), f2tf_f(hv[1]));
            } else {
                size_t HS = (size_t)Lt * Bt * Hd;
                if ((size_t)out_size >= HS + 2 * (size_t)Bt * Hd) {
                    *(float2*)&out[HS + (size_t)b * Hd + u0] =
                        make_float2(hv[0], hv[1]);
                    *(float2*)&out[HS + (size_t)Bt * Hd + (size_t)b * Hd + u0] =
                        make_float2(cv[0], cv[1]);
                }
            }
        }
        if (t + 1 < Lt) gbar((unsigned)(t + 2));
    }
}

extern "C" void kernel_launch(void* const* d_in, const int* in_sizes, int n_in,
                              void* d_out, int out_size) {
    (void)in_sizes; (void)n_in;
    const float* act = (const float*)d_in[0];   // action_features [L,B,A]
    const float* inp = (const float*)d_in[1];   // input_feature  [B,I]
    const float* h0  = (const float*)d_in[2];   // hidden_state   [B,H]
    const float* c0  = (const float*)d_in[3];   // state (c0)     [B,H]
    const float* Wih = (const float*)d_in[4];   // [4H, I+A]
    const float* Whh = (const float*)d_in[5];   // [4H, H]
    const float* bih = (const float*)d_in[6];   // [4H]
    const float* bhh = (const float*)d_in[7];   // [4H]
    float* out = (float*)d_out;

    cudaFuncSetAttribute(lstm_seq_kernel,
                         cudaFuncAttributeMaxDynamicSharedMemorySize, SMEM2);

    dim3 g1(Gd / BN, (Lt * Bt) / BM);           // (32, 128)
    gemm_x_kernel<<<g1, 256>>>(act, inp, Wih);
    lstm_seq_kernel<<<128, NTHR, SMEM2>>>(h0, c0, Whh, bih, bhh, out, out_size);
}

// round 2
// speedup vs baseline: 1.7081x; 1.7081x over previous
#include <cuda_runtime.h>
#include <cstdint>

// Problem dims
constexpr int Lt = 128;
constexpr int Bt = 128;
constexpr int Hd = 1024;
constexpr int Gd = 4 * Hd;       // 4096
constexpr int KA = 512;          // K of both sub-GEMMs (act part / input part)

// Static scratch
__device__ float g_gx_act[(size_t)Lt * Bt * Gd];   // act-side gate projections
__device__ float g_gx_inp[(size_t)Bt * Gd];        // input-side (t-invariant)
__device__ float g_hbuf[2][Bt * Hd];
__device__ unsigned g_bar_count;
__device__ unsigned g_bar_gen;

// ---------------------------------------------------------------- helpers
__device__ __forceinline__ uint32_t f2tf(float x) {
    uint32_t u; asm("cvt.rna.tf32.f32 %0, %1;" : "=r"(u) : "f"(x)); return u;
}
__device__ __forceinline__ float f2tf_f(float x) { return __uint_as_float(f2tf(x)); }
__device__ __forceinline__ uint32_t rtf(uint32_t r) {
    uint32_t u; asm("cvt.rna.tf32.f32 %0, %1;" : "=r"(u) : "f"(__uint_as_float(r)));
    return u;
}

__device__ __forceinline__ void mma8(float* c, const uint32_t* a,
                                     uint32_t b0, uint32_t b1) {
    asm volatile(
        "mma.sync.aligned.m16n8k8.row.col.f32.tf32.tf32.f32 "
        "{%0,%1,%2,%3},{%4,%5,%6,%7},{%8,%9},{%0,%1,%2,%3};"
        : "+f"(c[0]), "+f"(c[1]), "+f"(c[2]), "+f"(c[3])
        : "r"(a[0]), "r"(a[1]), "r"(a[2]), "r"(a[3]), "r"(b0), "r"(b1));
}

__device__ __forceinline__ void ldsm4(uint32_t& d0, uint32_t& d1,
                                      uint32_t& d2, uint32_t& d3, uint32_t a) {
    asm volatile("ldmatrix.sync.aligned.m8n8.x4.shared.b16 {%0,%1,%2,%3}, [%4];"
                 : "=r"(d0), "=r"(d1), "=r"(d2), "=r"(d3) : "r"(a));
}

__device__ __forceinline__ void cpa16(uint32_t d, const void* s) {
    asm volatile("cp.async.cg.shared.global [%0], [%1], 16;" :: "r"(d), "l"(s));
}
__device__ __forceinline__ void cpcommit() { asm volatile("cp.async.commit_group;"); }
template<int N> __device__ __forceinline__ void cpwait() {
    asm volatile("cp.async.wait_group %0;" :: "n"(N));
}
__device__ __forceinline__ uint32_t s2u(const void* p) {
    return (uint32_t)__cvta_generic_to_shared(p);
}
__device__ __forceinline__ float sigm(float x) { return 1.0f / (1.0f + expf(-x)); }

// ============================================================================
// Phase 1: tf32 GEMM, BM=BN=128, BK=32, 3-stage cp.async, ldmatrix frags.
// grid (32, 129): y<128 -> act GEMM tile (M=L*B, K=512, cols 512..1023 of W_ih)
//                 y==128 -> input GEMM (M=B, K=512, cols 0..511 of W_ih)
// smem tile layout: row-major rows of 8 16B-chunks, chunk XOR-swizzled by row&7
// ============================================================================
constexpr int BK1 = 32, STG = 3;
constexpr int STAGE_B = 128 * 32 * 4;               // 16 KB per operand stage
constexpr int SMEM1 = 2 * STG * STAGE_B;            // 96 KB

__global__ void __launch_bounds__(256, 2) gemm_x_kernel(
    const float* __restrict__ act, const float* __restrict__ inp,
    const float* __restrict__ Wih)
{
    if (blockIdx.x == 0 && blockIdx.y == 0 && threadIdx.x == 0) {
        g_bar_count = 0; g_bar_gen = 0;
    }
    extern __shared__ float sm1[];
    const uint32_t sA = s2u(sm1);
    const uint32_t sB = sA + STG * STAGE_B;

    const int tid = threadIdx.x, lane = tid & 31, warp = tid >> 5;
    const int wm = warp & 3, wn = warp >> 2;
    const bool isInp = (blockIdx.y == 128);
    const int bm = isInp ? 0 : blockIdx.y * 128;
    const int bn = blockIdx.x * 128;
    const float* Ab = isInp ? inp : act + (size_t)bm * KA;
    const int wcol = isInp ? 0 : 512;
    float* Cb = isInp ? g_gx_inp : g_gx_act + (size_t)bm * Gd;

    // cp.async mapping: thread -> (row, 4 consecutive 16B chunks)
    const int ldrow = tid >> 1, cbb = (tid & 1) * 4;
    const float* aSrc = Ab + (size_t)ldrow * KA + cbb * 4;
    const float* bSrc = Wih + (size_t)(bn + ldrow) * 1024 + wcol + cbb * 4;
    const uint32_t dRa = sA + ((uint32_t)ldrow << 7);
    const uint32_t dRb = sB + ((uint32_t)ldrow << 7);
    const int rlo = ldrow & 7;

    auto load = [&](int stage, int kb) {
        const float* as = aSrc + kb;
        const float* bs = bSrc + kb;
        uint32_t da = dRa + stage * STAGE_B;
        uint32_t db = dRb + stage * STAGE_B;
        #pragma unroll
        for (int j = 0; j < 4; j++) {
            int ch = cbb + j;
            cpa16(da + (uint32_t)((ch ^ rlo) << 4), as + j * 4);
            cpa16(db + (uint32_t)((ch ^ rlo) << 4), bs + j * 4);
        }
    };

    load(0, 0); cpcommit();
    load(1, BK1); cpcommit();

    float acc[2][8][4];
    #pragma unroll
    for (int i = 0; i < 2; i++)
        #pragma unroll
        for (int j = 0; j < 8; j++)
            #pragma unroll
            for (int k = 0; k < 4; k++) acc[i][j][k] = 0.0f;

    // ldmatrix per-lane geometry
    const int lrow = lane & 7, grp = lane >> 3;
    const int aro = ((grp & 1) << 3) + lrow, acs = grp >> 1;   // A tiles
    const int bro = ((grp >> 1) << 3) + lrow, bcs = grp & 1;   // B tiles

    for (int kb = 0; kb < KA / BK1; kb++) {           // 16 iterations
        cpwait<1>(); __syncthreads();
        if (kb + 2 < KA / BK1) load((kb + 2) % 3, (kb + 2) * BK1);
        cpcommit();
        const uint32_t stA = sA + (kb % 3) * STAGE_B;
        const uint32_t stB = sB + (kb % 3) * STAGE_B;

        #pragma unroll
        for (int ks = 0; ks < 4; ks++) {
            const int kc = 2 * ks;
            uint32_t a[2][4];
            #pragma unroll
            for (int tm = 0; tm < 2; tm++) {
                int row = wm * 32 + tm * 16 + aro;
                ldsm4(a[tm][0], a[tm][1], a[tm][2], a[tm][3],
                      stA + (uint32_t)(((row << 3) + ((kc + acs) ^ lrow)) << 4));
            }
            uint32_t b[4][4];
            #pragma unroll
            for (int p = 0; p < 4; p++) {
                int row = wn * 64 + p * 16 + bro;
                ldsm4(b[p][0], b[p][1], b[p][2], b[p][3],
                      stB + (uint32_t)(((row << 3) + ((kc + bcs) ^ lrow)) << 4));
            }
            #pragma unroll
            for (int tm = 0; tm < 2; tm++)
                #pragma unroll
                for (int i = 0; i < 4; i++) a[tm][i] = rtf(a[tm][i]);
            #pragma unroll
            for (int p = 0; p < 4; p++)
                #pragma unroll
                for (int i = 0; i < 4; i++) b[p][i] = rtf(b[p][i]);
            #pragma unroll
            for (int p = 0; p < 4; p++)
                #pragma unroll
                for (int tm = 0; tm < 2; tm++) {
                    mma8(acc[tm][2 * p],     a[tm], b[p][0], b[p][1]);
                    mma8(acc[tm][2 * p + 1], a[tm], b[p][2], b[p][3]);
                }
        }
    }

    // epilogue
    #pragma unroll
    for (int tm = 0; tm < 2; tm++) {
        int r = wm * 32 + tm * 16 + (lane >> 2);
        #pragma unroll
        for (int tn = 0; tn < 8; tn++) {
            int cc = bn + wn * 64 + tn * 8 + 2 * (lane & 3);
            *(float2*)&Cb[(size_t)r * Gd + cc] =
                make_float2(acc[tm][tn][0], acc[tm][tn][1]);
            *(float2*)&Cb[(size_t)(r + 8) * Gd + cc] =
                make_float2(acc[tm][tn][2], acc[tm][tn][3]);
        }
    }
}

// ============================================================================
// Phase 2: persistent LSTM recurrence (128 CTAs, 1/SM).
// W_hh slice in smem (tf32, ldmatrix-friendly), h staged via 2-stage cp.async,
// mma frags via ldmatrix, c-state in registers, one grid barrier per step.
// ============================================================================
constexpr int NTHR = 256;
constexpr int WPAD = Hd + 4;                        // 1028
constexpr int WS_B = 32 * WPAD * 4;                 // 131584 B
constexpr int HT_STAGE_B = 128 * 32 * 4;            // 16384 B
constexpr int SMEM2 = WS_B + 2 * HT_STAGE_B;        // 164352 B

__device__ __forceinline__ void gbar(unsigned target) {
    __syncthreads();
    if (threadIdx.x == 0) {
        __threadfence();
        unsigned old = atomicAdd(&g_bar_count, 1u);
        if ((old + 1u) % gridDim.x == 0u) {
            __threadfence();
            asm volatile("red.release.gpu.global.add.u32 [%0], %1;"
                         :: "l"(&g_bar_gen), "r"(1u) : "memory");
        } else {
            unsigned g;
            do {
                asm volatile("ld.acquire.gpu.global.u32 %0, [%1];"
                             : "=r"(g) : "l"(&g_bar_gen) : "memory");
            } while (g < target);
        }
        __threadfence();
    }
    __syncthreads();
}

__global__ void __launch_bounds__(NTHR, 1) lstm_seq_kernel(
    const float* __restrict__ h0, const float* __restrict__ c0in,
    const float* __restrict__ Whh, const float* __restrict__ bih,
    const float* __restrict__ bhh, float* __restrict__ out, int out_size)
{
    extern __shared__ float smemf[];
    float* Ws = smemf;                              // [32][1028]
    const uint32_t sWs = s2u(smemf);
    const uint32_t sHt = sWs + WS_B;

    const int tid = threadIdx.x, lane = tid & 31, warp = tid >> 5;
    const int cta = blockIdx.x;
    const int ub  = cta * 8;
    const int u0  = ub + 2 * (lane & 3);
    const int b0  = warp * 16 + (lane >> 2);

    // W_hh slice -> smem, tf32-rounded. local rows: gate*8 + unit
    for (int i = tid; i < 32 * (Hd / 4); i += NTHR) {
        int lr = i >> 8;
        int c4 = (i & 255) * 4;
        int grow = (lr >> 3) * Hd + ub + (lr & 7);
        float4 v = *(const float4*)&Whh[(size_t)grow * Hd + c4];
        float* d = &Ws[lr * WPAD + c4];
        d[0] = f2tf_f(v.x); d[1] = f2tf_f(v.y); d[2] = f2tf_f(v.z); d[3] = f2tf_f(v.w);
    }

    // t-invariant gate term: input-projection + both biases (registers)
    float2 gxi[4][2];
    #pragma unroll
    for (int q = 0; q < 4; q++) {
        float bx = bih[q * Hd + u0]     + bhh[q * Hd + u0];
        float by = bih[q * Hd + u0 + 1] + bhh[q * Hd + u0 + 1];
        #pragma unroll
        for (int bs = 0; bs < 2; bs++) {
            int b = b0 + bs * 8;
            float2 v = *(const float2*)&g_gx_inp[(size_t)b * Gd + q * Hd + u0];
            gxi[q][bs] = make_float2(v.x + bx, v.y + by);
        }
    }

    float creg[2][2];
    #pragma unroll
    for (int bs = 0; bs < 2; bs++) {
        int b = b0 + bs * 8;
        creg[bs][0] = c0in[(size_t)b * Hd + u0];
        creg[bs][1] = c0in[(size_t)b * Hd + u0 + 1];
    }

    for (int i = tid; i < Hd; i += NTHR)
        g_hbuf[0][cta * Hd + i] = f2tf_f(h0[cta * Hd + i]);
    gbar(1);

    // staging + ldmatrix geometry
    const int ldrow = tid >> 1, cbb = (tid & 1) * 4;
    const int rlo = ldrow & 7;
    const int lrow = lane & 7, grp = lane >> 3;
    const int aro = ((grp & 1) << 3) + lrow, acs = grp >> 1;

    for (int t = 0; t < Lt; t++) {
        const float* cur = g_hbuf[t & 1];
        float* nxt = g_hbuf[(t + 1) & 1];

        float2 gxa[4][2];
        #pragma unroll
        for (int q = 0; q < 4; q++)
            #pragma unroll
            for (int bs = 0; bs < 2; bs++) {
                int b = b0 + bs * 8;
                gxa[q][bs] = *(const float2*)
                    &g_gx_act[((size_t)t * Bt + b) * Gd + q * Hd + u0];
            }

        float acc[4][4];
        #pragma unroll
        for (int q = 0; q < 4; q++)
            #pragma unroll
            for (int k = 0; k < 4; k++) acc[q][k] = 0.0f;

        // stage kb=0
        {
            const float* s = cur + (size_t)ldrow * Hd + cbb * 4;
            uint32_t d = sHt + ((uint32_t)ldrow << 7);
            #pragma unroll
            for (int j = 0; j < 4; j++)
                cpa16(d + (uint32_t)(((cbb + j) ^ rlo) << 4), s + j * 4);
        }
        cpcommit();

        for (int kb = 0; kb < 32; kb++) {
            cpwait<0>(); __syncthreads();
            if (kb < 31) {
                const float* s = cur + (size_t)ldrow * Hd + (kb + 1) * 32 + cbb * 4;
                uint32_t d = sHt + ((kb + 1) & 1) * HT_STAGE_B + ((uint32_t)ldrow << 7);
                #pragma unroll
                for (int j = 0; j < 4; j++)
                    cpa16(d + (uint32_t)(((cbb + j) ^ rlo) << 4), s + j * 4);
            }
            cpcommit();

            const uint32_t stb = sHt + (kb & 1) * HT_STAGE_B;
            #pragma unroll
            for (int h = 0; h < 2; h++) {
                uint32_t bf[4][4];
                #pragma unroll
                for (int q = 0; q < 4; q++) {
                    uint32_t ba = sWs + (uint32_t)(((q * 8 + lrow) * WPAD
                                      + kb * 32 + (4 * h + grp) * 4) << 2);
                    ldsm4(bf[q][0], bf[q][1], bf[q][2], bf[q][3], ba);
                }
                #pragma unroll
                for (int sub = 0; sub < 2; sub++) {
                    const int kc = 4 * h + 2 * sub;
                    uint32_t a[4];
                    int row = warp * 16 + aro;
                    ldsm4(a[0], a[1], a[2], a[3],
                          stb + (uint32_t)(((row << 3) + ((kc + acs) ^ lrow)) << 4));
                    #pragma unroll
                    for (int q = 0; q < 4; q++)
                        mma8(acc[q], a, bf[q][2 * sub], bf[q][2 * sub + 1]);
                }
            }
        }

        // cell update (all 4 gates of a unit live in this thread)
        #pragma unroll
        for (int bs = 0; bs < 2; bs++) {
            int b = b0 + bs * 8;
            float hv[2], cv[2];
            #pragma unroll
            for (int us = 0; us < 2; us++) {
                int ci = bs * 2 + us;
                float gi = acc[0][ci] + (us ? gxa[0][bs].y : gxa[0][bs].x)
                                      + (us ? gxi[0][bs].y : gxi[0][bs].x);
                float gf = acc[1][ci] + (us ? gxa[1][bs].y : gxa[1][bs].x)
                                      + (us ? gxi[1][bs].y : gxi[1][bs].x);
                float gg = acc[2][ci] + (us ? gxa[2][bs].y : gxa[2][bs].x)
                                      + (us ? gxi[2][bs].y : gxi[2][bs].x);
                float go = acc[3][ci] + (us ? gxa[3][bs].y : gxa[3][bs].x)
                                      + (us ? gxi[3][bs].y : gxi[3][bs].x);
                float cn = sigm(gf) * creg[bs][us] + sigm(gi) * tanhf(gg);
                float hn = sigm(go) * tanhf(cn);
                creg[bs][us] = cn;
                hv[us] = hn; cv[us] = cn;
            }
            size_t ob = (size_t)t * Bt * Hd + (size_t)b * Hd + u0;
            *(float2*)&out[ob] = make_float2(hv[0], hv[1]);
            if (t + 1 < Lt) {
                *(float2*)&nxt[b * Hd + u0] =
                    make_float2(f2tf_f(hv[0]), f2tf_f(hv[1]));
            } else {
                size_t HS = (size_t)Lt * Bt * Hd;
                if ((size_t)out_size >= HS + 2 * (size_t)Bt * Hd) {
                    *(float2*)&out[HS + (size_t)b * Hd + u0] =
                        make_float2(hv[0], hv[1]);
                    *(float2*)&out[HS + (size_t)Bt * Hd + (size_t)b * Hd + u0] =
                        make_float2(cv[0], cv[1]);
                }
            }
        }
        if (t + 1 < Lt) gbar((unsigned)(t + 2));
    }
}

extern "C" void kernel_launch(void* const* d_in, const int* in_sizes, int n_in,
                              void* d_out, int out_size) {
    (void)in_sizes; (void)n_in;
    const float* act = (const float*)d_in[0];
    const float* inp = (const float*)d_in[1];
    const float* h0  = (const float*)d_in[2];
    const float* c0  = (const float*)d_in[3];
    const float* Wih = (const float*)d_in[4];
    const float* Whh = (const float*)d_in[5];
    const float* bih = (const float*)d_in[6];
    const float* bhh = (const float*)d_in[7];
    float* out = (float*)d_out;

    cudaFuncSetAttribute(gemm_x_kernel,
                         cudaFuncAttributeMaxDynamicSharedMemorySize, SMEM1);
    cudaFuncSetAttribute(lstm_seq_kernel,
                         cudaFuncAttributeMaxDynamicSharedMemorySize, SMEM2);

    gemm_x_kernel<<<dim3(32, 129), 256, SMEM1>>>(act, inp, Wih);
    lstm_seq_kernel<<<128, NTHR, SMEM2>>>(h0, c0, Whh, bih, bhh, out, out_size);
}

// round 5
// speedup vs baseline: 2.1938x; 1.2844x over previous
#include <cuda_runtime.h>
#include <cuda_fp16.h>
#include <cstdint>

// Problem dims
constexpr int Lt = 128;
constexpr int Bt = 128;
constexpr int Hd = 1024;
constexpr int Gd = 4 * Hd;       // 4096
constexpr int KA = 512;          // K of both phase-1 sub-GEMMs

// Static scratch
__device__ float g_gx_act[(size_t)Lt * Bt * Gd];     // act-side gate projections
__device__ float g_gx_inp[(size_t)Bt * Gd];          // input-side (t-invariant)
__device__ __align__(16) __half g_act_h[(size_t)Lt * Bt * KA];
__device__ __align__(16) __half g_inp_h[(size_t)Bt * KA];
__device__ __align__(16) __half g_wih_h[(size_t)Gd * 1024];
__device__ __align__(16) __half g_hbuf_h[2][Bt * Hd];
__device__ unsigned g_bar_count;
__device__ unsigned g_bar_gen;

// ---------------------------------------------------------------- helpers
__device__ __forceinline__ uint32_t h2u(__half2 v) {
    __half2_raw r = *(__half2_raw*)&v;
    return (uint32_t)r.x | ((uint32_t)r.y << 16);
}
__device__ __forceinline__ void mma16(float* c, const uint32_t* a,
                                      uint32_t b0, uint32_t b1) {
    asm volatile(
        "mma.sync.aligned.m16n8k16.row.col.f32.f16.f16.f32 "
        "{%0,%1,%2,%3},{%4,%5,%6,%7},{%8,%9},{%0,%1,%2,%3};"
        : "+f"(c[0]), "+f"(c[1]), "+f"(c[2]), "+f"(c[3])
        : "r"(a[0]), "r"(a[1]), "r"(a[2]), "r"(a[3]), "r"(b0), "r"(b1));
}
__device__ __forceinline__ void ldsm4(uint32_t& d0, uint32_t& d1,
                                      uint32_t& d2, uint32_t& d3, uint32_t a) {
    asm volatile("ldmatrix.sync.aligned.m8n8.x4.shared.b16 {%0,%1,%2,%3}, [%4];"
                 : "=r"(d0), "=r"(d1), "=r"(d2), "=r"(d3) : "r"(a));
}
__device__ __forceinline__ void cpa16(uint32_t d, const void* s) {
    asm volatile("cp.async.cg.shared.global [%0], [%1], 16;" :: "r"(d), "l"(s));
}
__device__ __forceinline__ void cpcommit() { asm volatile("cp.async.commit_group;"); }
template<int N> __device__ __forceinline__ void cpwait() {
    asm volatile("cp.async.wait_group %0;" :: "n"(N));
}
__device__ __forceinline__ uint32_t s2u(const void* p) {
    return (uint32_t)__cvta_generic_to_shared(p);
}
__device__ __forceinline__ float sigm(float x) { return 1.0f / (1.0f + expf(-x)); }

// ============================================================================
// Prep: fp16-convert act / inp / W_ih into static buffers; reset grid barrier.
// ============================================================================
__global__ void prep_kernel(const float* __restrict__ act,
                            const float* __restrict__ inp,
                            const float* __restrict__ Wih) {
    if (blockIdx.x == 0 && threadIdx.x == 0) { g_bar_count = 0; g_bar_gen = 0; }
    const size_t NW = (size_t)Gd * 1024 / 8;      // 8-elem groups
    const size_t NA = (size_t)Lt * Bt * KA / 8;
    const size_t NI = (size_t)Bt * KA / 8;
    const size_t total = NW + NA + NI;
    for (size_t i = (size_t)blockIdx.x * blockDim.x + threadIdx.x; i < total;
         i += (size_t)gridDim.x * blockDim.x) {
        const float4* s; uint4* d;
        if (i < NW)           { s = (const float4*)Wih + 2 * i;            d = (uint4*)g_wih_h + i; }
        else if (i < NW + NA) { s = (const float4*)act + 2 * (i - NW);     d = (uint4*)g_act_h + (i - NW); }
        else                  { s = (const float4*)inp + 2 * (i - NW - NA); d = (uint4*)g_inp_h + (i - NW - NA); }
        float4 v0 = s[0], v1 = s[1];
        uint4 o;
        o.x = h2u(__floats2half2_rn(v0.x, v0.y));
        o.y = h2u(__floats2half2_rn(v0.z, v0.w));
        o.z = h2u(__floats2half2_rn(v1.x, v1.y));
        o.w = h2u(__floats2half2_rn(v1.z, v1.w));
        *d = o;
    }
}

// ============================================================================
// Phase 1: fp16 m16n8k16 GEMM. BM=BN=128, BK=32, 4-stage cp.async, ldmatrix.
// Smem layout: array of 8x8-half tiles, 128B each, 16B slots XOR-swizzled by
// the tile's k-chunk index (conflict-free ldmatrix, low-conflict stores).
// grid (32, 129): y<128 -> act tile (W cols 512..), y==128 -> input tile.
// ============================================================================
constexpr int P1_STG = 4;
constexpr int P1_STAGE_B = 2 * 128 * 32 * 2;   // A 8KB + B 8KB = 16 KB
constexpr int P1_SMEM = P1_STG * P1_STAGE_B;   // 64 KB

__global__ void __launch_bounds__(256, 2) gemm_x_h() {
    extern __shared__ char sm1[];
    const uint32_t sBase = s2u(sm1);

    const int tid = threadIdx.x, lane = tid & 31, warp = tid >> 5;
    const int wm = warp & 3, wn = warp >> 2;
    const bool isInp = (blockIdx.y == 128);
    const int bm = isInp ? 0 : blockIdx.y * 128;
    const int bn = blockIdx.x * 128;
    const __half* Ab = isInp ? g_inp_h : g_act_h + (size_t)bm * KA;
    const __half* Bb = g_wih_h + (size_t)bn * 1024 + (isInp ? 0 : 512);
    float* Cb = isInp ? g_gx_inp : g_gx_act + (size_t)bm * Gd;

    const int r = tid >> 1;              // staging row 0..127
    const int cpair = (tid & 1) * 2;     // 2 chunks of 8 halves
    const __half* aRow = Ab + (size_t)r * KA;
    const __half* bRow = Bb + (size_t)r * 1024;

    auto loadblk = [&](int kb) {
        if (kb < 16) {
            uint32_t st = sBase + (uint32_t)(kb & 3) * P1_STAGE_B;
            const __half* a = aRow + kb * 32;
            const __half* b = bRow + kb * 32;
            #pragma unroll
            for (int j = 0; j < 2; j++) {
                int c = cpair + j;
                uint32_t off = (uint32_t)(((r >> 3) * 4 + c) * 128)
                             + (uint32_t)((((r & 7) ^ c) * 16));
                cpa16(st + off, a + c * 8);
                cpa16(st + 8192 + off, b + c * 8);
            }
        }
        cpcommit();
    };

    loadblk(0); loadblk(1); loadblk(2);

    float acc[2][8][4];
    #pragma unroll
    for (int i = 0; i < 2; i++)
        #pragma unroll
        for (int j = 0; j < 8; j++)
            #pragma unroll
            for (int k = 0; k < 4; k++) acc[i][j][k] = 0.0f;

    const int g = lane >> 3;             // lane group 0..3
    const int l7 = lane & 7;

    for (int kb = 0; kb < 16; kb++) {
        cpwait<2>(); __syncthreads();
        loadblk(kb + 3);
        const uint32_t stA = sBase + (uint32_t)(kb & 3) * P1_STAGE_B;
        const uint32_t stB = stA + 8192;

        #pragma unroll
        for (int kc = 0; kc < 2; kc++) {
            uint32_t a[2][4];
            #pragma unroll
            for (int tm = 0; tm < 2; tm++) {
                int rt = wm * 4 + tm * 2 + (g & 1);
                int ct = kc * 2 + (g >> 1);
                ldsm4(a[tm][0], a[tm][1], a[tm][2], a[tm][3],
                      stA + (uint32_t)((rt * 4 + ct) * 128 + ((l7 ^ ct) * 16)));
            }
            #pragma unroll
            for (int j = 0; j < 4; j++) {
                int nt = wn * 8 + 2 * j + (g >> 1);
                int ct = kc * 2 + (g & 1);
                uint32_t b0, b1, b2, b3;
                ldsm4(b0, b1, b2, b3,
                      stB + (uint32_t)((nt * 4 + ct) * 128 + ((l7 ^ ct) * 16)));
                mma16(acc[0][2 * j],     a[0], b0, b1);
                mma16(acc[0][2 * j + 1], a[0], b2, b3);
                mma16(acc[1][2 * j],     a[1], b0, b1);
                mma16(acc[1][2 * j + 1], a[1], b2, b3);
            }
        }
    }

    // epilogue
    #pragma unroll
    for (int tm = 0; tm < 2; tm++) {
        int rr = wm * 32 + tm * 16 + (lane >> 2);
        #pragma unroll
        for (int tn = 0; tn < 8; tn++) {
            int cc = bn + wn * 64 + tn * 8 + 2 * (lane & 3);
            *(float2*)&Cb[(size_t)rr * Gd + cc] =
                make_float2(acc[tm][tn][0], acc[tm][tn][1]);
            *(float2*)&Cb[(size_t)(rr + 8) * Gd + cc] =
                make_float2(acc[tm][tn][2], acc[tm][tn][3]);
        }
    }
}

// ============================================================================
// Phase 2: persistent LSTM recurrence (128 CTAs, 1/SM), fp16 mma.
// W_hh slice fp16 in smem (64 KB, tile-native layout); h broadcast in fp16
// (halves L2 traffic); h staged via 4-stage cp.async; c-state in registers.
// ============================================================================
constexpr int NTHR = 256;
constexpr int WS_B = 32 * 1024 * 2;             // 64 KB W tiles
constexpr int HT_STAGE_B = 128 * 64 * 2;        // 16 KB per h stage
constexpr int SMEM2 = WS_B + 4 * HT_STAGE_B;    // 128 KB

__device__ __forceinline__ void gbar(unsigned target) {
    __syncthreads();
    if (threadIdx.x == 0) {
        __threadfence();
        unsigned old = atomicAdd(&g_bar_count, 1u);
        if ((old + 1u) % gridDim.x == 0u) {
            __threadfence();
            asm volatile("red.release.gpu.global.add.u32 [%0], %1;"
                         :: "l"(&g_bar_gen), "r"(1u) : "memory");
        } else {
            unsigned gg;
            do {
                asm volatile("ld.acquire.gpu.global.u32 %0, [%1];"
                             : "=r"(gg) : "l"(&g_bar_gen) : "memory");
            } while (gg < target);
        }
        __threadfence();
    }
    __syncthreads();
}

__global__ void __launch_bounds__(NTHR, 1) lstm_seq_kernel(
    const float* __restrict__ h0, const float* __restrict__ c0in,
    const float* __restrict__ Whh, const float* __restrict__ bih,
    const float* __restrict__ bhh, float* __restrict__ out, int out_size)
{
    extern __shared__ char sm2[];
    const uint32_t sW = s2u(sm2);
    const uint32_t sSt = sW + WS_B;

    const int tid = threadIdx.x, lane = tid & 31, warp = tid >> 5;
    const int cta = blockIdx.x;
    const int ub  = cta * 8;
    const int u0  = ub + 2 * (lane & 3);
    const int b0  = warp * 16 + (lane >> 2);

    // --- W_hh slice -> smem fp16, tile-native: tile(gate, ctg) of 8x8 halves,
    // 16B slot swizzled by ctg&7. local row lr = gate*8 + unit.
    for (int i = tid; i < 32 * 128; i += NTHR) {
        int lr = i >> 7;          // 0..31
        int c  = i & 127;         // k-chunk (8 halves)
        int gate = lr >> 3, unit = lr & 7;
        const float* src = Whh + (size_t)(gate * Hd + ub + unit) * Hd + c * 8;
        float4 v0 = *(const float4*)src;
        float4 v1 = *(const float4*)(src + 4);
        uint4 o;
        o.x = h2u(__floats2half2_rn(v0.x, v0.y));
        o.y = h2u(__floats2half2_rn(v0.z, v0.w));
        o.z = h2u(__floats2half2_rn(v1.x, v1.y));
        o.w = h2u(__floats2half2_rn(v1.z, v1.w));
        uint32_t off = (uint32_t)((gate * 128 + c) * 128 + ((unit ^ (c & 7)) * 16));
        *(uint4*)(sm2 + off) = o;
    }

    // t-invariant gate term: input-projection + both biases
    float2 gxi[4][2];
    #pragma unroll
    for (int q = 0; q < 4; q++) {
        float bx = bih[q * Hd + u0]     + bhh[q * Hd + u0];
        float by = bih[q * Hd + u0 + 1] + bhh[q * Hd + u0 + 1];
        #pragma unroll
        for (int bs = 0; bs < 2; bs++) {
            int b = b0 + bs * 8;
            float2 v = *(const float2*)&g_gx_inp[(size_t)b * Gd + q * Hd + u0];
            gxi[q][bs] = make_float2(v.x + bx, v.y + by);
        }
    }

    float creg[2][2];
    #pragma unroll
    for (int bs = 0; bs < 2; bs++) {
        int b = b0 + bs * 8;
        creg[bs][0] = c0in[(size_t)b * Hd + u0];
        creg[bs][1] = c0in[(size_t)b * Hd + u0 + 1];
    }

    // initial h broadcast (each CTA writes one batch row, fp16)
    for (int i = tid; i < Hd / 2; i += NTHR) {
        float2 v = *(const float2*)&h0[(size_t)cta * Hd + 2 * i];
        *(__half2*)&g_hbuf_h[0][cta * Hd + 2 * i] = __floats2half2_rn(v.x, v.y);
    }
    gbar(1);

    // staging + ldmatrix geometry
    const int sr = tid >> 1;                 // staging row 0..127
    const int scb = (tid & 1) * 4;           // 4 chunks of 8 halves
    const int g = lane >> 3, l7 = lane & 7;

    for (int t = 0; t < Lt; t++) {
        const __half* cur = g_hbuf_h[t & 1];
        __half* nxt = g_hbuf_h[(t + 1) & 1];

        float2 gxa[4][2];
        #pragma unroll
        for (int q = 0; q < 4; q++)
            #pragma unroll
            for (int bs = 0; bs < 2; bs++) {
                int b = b0 + bs * 8;
                gxa[q][bs] = *(const float2*)
                    &g_gx_act[((size_t)t * Bt + b) * Gd + q * Hd + u0];
            }

        float acc[4][4];
        #pragma unroll
        for (int q = 0; q < 4; q++)
            #pragma unroll
            for (int k = 0; k < 4; k++) acc[q][k] = 0.0f;

        auto stage = [&](int kb) {
            if (kb < 16) {
                uint32_t st = sSt + (uint32_t)(kb & 3) * HT_STAGE_B;
                const __half* s = cur + (size_t)sr * Hd + kb * 64;
                #pragma unroll
                for (int j = 0; j < 4; j++) {
                    int c = scb + j;
                    uint32_t off = (uint32_t)(((sr >> 3) * 8 + c) * 128
                                 + (((sr & 7) ^ (c & 7)) * 16));
                    cpa16(st + off, s + c * 8);
                }
            }
            cpcommit();
        };

        stage(0); stage(1); stage(2);

        for (int kb = 0; kb < 16; kb++) {
            cpwait<2>(); __syncthreads();
            stage(kb + 3);
            const uint32_t st = sSt + (uint32_t)(kb & 3) * HT_STAGE_B;

            #pragma unroll
            for (int kc = 0; kc < 4; kc++) {
                uint32_t a[4];
                {
                    int rt = warp * 2 + (g & 1);
                    int ct = kc * 2 + (g >> 1);
                    ldsm4(a[0], a[1], a[2], a[3],
                          st + (uint32_t)((rt * 8 + ct) * 128 + ((l7 ^ ct) * 16)));
                }
                #pragma unroll
                for (int p = 0; p < 2; p++) {
                    int gate = 2 * p + (g >> 1);
                    int ctg = kb * 8 + kc * 2 + (g & 1);
                    uint32_t b0r, b1r, b2r, b3r;
                    ldsm4(b0r, b1r, b2r, b3r,
                          sW + (uint32_t)((gate * 128 + ctg) * 128
                               + ((l7 ^ (ctg & 7)) * 16)));
                    mma16(acc[2 * p],     a, b0r, b1r);
                    mma16(acc[2 * p + 1], a, b2r, b3r);
                }
            }
        }

        // cell update (all 4 gates of a unit live in this thread)
        #pragma unroll
        for (int bs = 0; bs < 2; bs++) {
            int b = b0 + bs * 8;
            float hv[2], cv[2];
            #pragma unroll
            for (int us = 0; us < 2; us++) {
                int ci = bs * 2 + us;
                float gi = acc[0][ci] + (us ? gxa[0][bs].y : gxa[0][bs].x)
                                      + (us ? gxi[0][bs].y : gxi[0][bs].x);
                float gf = acc[1][ci] + (us ? gxa[1][bs].y : gxa[1][bs].x)
                                      + (us ? gxi[1][bs].y : gxi[1][bs].x);
                float gg = acc[2][ci] + (us ? gxa[2][bs].y : gxa[2][bs].x)
                                      + (us ? gxi[2][bs].y : gxi[2][bs].x);
                float go = acc[3][ci] + (us ? gxa[3][bs].y : gxa[3][bs].x)
                                      + (us ? gxi[3][bs].y : gxi[3][bs].x);
                float cn = sigm(gf) * creg[bs][us] + sigm(gi) * tanhf(gg);
                float hn = sigm(go) * tanhf(cn);
                creg[bs][us] = cn;
                hv[us] = hn; cv[us] = cn;
            }
            size_t ob = (size_t)t * Bt * Hd + (size_t)b * Hd + u0;
            *(float2*)&out[ob] = make_float2(hv[0], hv[1]);
            if (t + 1 < Lt) {
                *(__half2*)&nxt[b * Hd + u0] = __floats2half2_rn(hv[0], hv[1]);
            } else {
                size_t HS = (size_t)Lt * Bt * Hd;
                if ((size_t)out_size >= HS + 2 * (size_t)Bt * Hd) {
                    *(float2*)&out[HS + (size_t)b * Hd + u0] =
                        make_float2(hv[0], hv[1]);
                    *(float2*)&out[HS + (size_t)Bt * Hd + (size_t)b * Hd + u0] =
                        make_float2(cv[0], cv[1]);
                }
            }
        }
        if (t + 1 < Lt) gbar((unsigned)(t + 2));
    }
}

extern "C" void kernel_launch(void* const* d_in, const int* in_sizes, int n_in,
                              void* d_out, int out_size) {
    (void)in_sizes; (void)n_in;
    const float* act = (const float*)d_in[0];
    const float* inp = (const float*)d_in[1];
    const float* h0  = (const float*)d_in[2];
    const float* c0  = (const float*)d_in[3];
    const float* Wih = (const float*)d_in[4];
    const float* Whh = (const float*)d_in[5];
    const float* bih = (const float*)d_in[6];
    const float* bhh = (const float*)d_in[7];
    float* out = (float*)d_out;

    cudaFuncSetAttribute(gemm_x_h,
                         cudaFuncAttributeMaxDynamicSharedMemorySize, P1_SMEM);
    cudaFuncSetAttribute(lstm_seq_kernel,
                         cudaFuncAttributeMaxDynamicSharedMemorySize, SMEM2);

    prep_kernel<<<1024, 256>>>(act, inp, Wih);
    gemm_x_h<<<dim3(32, 129), 256, P1_SMEM>>>();
    lstm_seq_kernel<<<128, NTHR, SMEM2>>>(h0, c0, Whh, bih, bhh, out, out_size);
}